// round 5
// baseline (speedup 1.0000x reference)
#include <cuda_runtime.h>
#include <cuda_bf16.h>
#include <cuda_fp8.h>
#include <math.h>
#include <stdint.h>

// ExamplarLoss fused, symmetric, FP8: S = Lhat@Lhat^T on upper-tri 128x128
// tiles via mma.m16n8k32 e4m3 (2x MACs/instr vs bf16). Data quantized as
// q = fp8(16*sqrt(log2e)*xhat) so acc = 256*log2(e)*S -> exp2(acc/256).
// Diagonal canceled with fp8-consistent sii; positive pair from bf16 copy.

#define NN 8192
#define DD 128
#define NB 64            // 64 row-blocks of 128

__device__ uint32_t g_fp8[NN * 32];     // fp8 rows, 128B/row (1 MB)  [GEMM operand]
__device__ uint4    g_bf4[NN * DD / 8]; // bf16*sqrt(log2e) rows (2 MB) [finrow pos]
__device__ float    g_rowsum[NN];       // per-row sum of exp2 (atomic accum)

#define SQRT_LOG2E 1.2011224087864498f
#define LN2F       0.6931471805599453f
#define FP8_SCALE  16.0f
#define INV_SC2    (1.0f / 256.0f)

// ------------------------- PTX helpers (base ISA) -------------------------
__device__ __forceinline__ uint32_t smem_u32(const void* p) {
    uint32_t a;
    asm("{ .reg .u64 t; cvta.to.shared.u64 t, %1; cvt.u32.u64 %0, t; }" : "=r"(a) : "l"(p));
    return a;
}
__device__ __forceinline__ void cp16(uint32_t dst, const void* src) {
    asm volatile("cp.async.cg.shared.global [%0], [%1], 16;" :: "r"(dst), "l"(src));
}
#define CP_COMMIT() asm volatile("cp.async.commit_group;" ::: "memory")
#define CP_WAIT0()  asm volatile("cp.async.wait_group 0;" ::: "memory")

__device__ __forceinline__ void ldsm4(uint32_t (&r)[4], uint32_t addr) {
    asm volatile("ldmatrix.sync.aligned.m8n8.x4.shared.b16 {%0,%1,%2,%3}, [%4];"
                 : "=r"(r[0]), "=r"(r[1]), "=r"(r[2]), "=r"(r[3]) : "r"(addr));
}
__device__ __forceinline__ void mma_fp8(float (&d)[4], const uint32_t (&a)[4],
                                        const uint32_t* b) {
    asm volatile("mma.sync.aligned.m16n8k32.row.col.f32.e4m3.e4m3.f32 "
                 "{%0,%1,%2,%3}, {%4,%5,%6,%7}, {%8,%9}, {%0,%1,%2,%3};"
                 : "+f"(d[0]), "+f"(d[1]), "+f"(d[2]), "+f"(d[3])
                 : "r"(a[0]), "r"(a[1]), "r"(a[2]), "r"(a[3]), "r"(b[0]), "r"(b[1]));
}

// ---------------- Phase 1: normalize -> fp8(16*c*x) + bf16(c*x); zero accums
__global__ void __launch_bounds__(256) prep_kernel(const float* __restrict__ l1,
                                                   const float* __restrict__ l2,
                                                   float* __restrict__ out) {
    const int row = blockIdx.x * 8 + (threadIdx.x >> 5);
    const int lane = threadIdx.x & 31;
    if (threadIdx.x < 8) g_rowsum[blockIdx.x * 8 + threadIdx.x] = 0.f;
    if (blockIdx.x == 0 && threadIdx.x == 0) out[0] = 0.f;

    const float* src = (row & 1) ? l2 : l1;
    const float4 v = ((const float4*)(src + (row >> 1) * DD))[lane];
    float sq = v.x * v.x + v.y * v.y + v.z * v.z + v.w * v.w;
    #pragma unroll
    for (int o = 16; o; o >>= 1) sq += __shfl_xor_sync(0xffffffffu, sq, o);
    const float inv = rsqrtf(sq) * SQRT_LOG2E;

    // bf16 copy (scale sqrt(log2e))
    __nv_bfloat162 p0 = __floats2bfloat162_rn(v.x * inv, v.y * inv);
    __nv_bfloat162 p1 = __floats2bfloat162_rn(v.z * inv, v.w * inv);
    uint2 packed;
    packed.x = *(uint32_t*)&p0;
    packed.y = *(uint32_t*)&p1;
    ((uint2*)g_bf4)[row * 32 + lane] = packed;

    // fp8 copy (scale 16*sqrt(log2e))
    const float f = inv * FP8_SCALE;
    __nv_fp8x4_e4m3 q4(make_float4(v.x * f, v.y * f, v.z * f, v.w * f));
    g_fp8[row * 32 + lane] = *(uint32_t*)&q4;
}

// ---------------- Phase 2: symmetric FP8 MMA + fused dual-sided sum-exp2
// SMEM: A 16KB | B 16KB | red_row 512B | red_col 512B
#define S_A    0
#define S_B    16384
#define S_RR   32768
#define S_RC   33280
#define S_TOT  33792

__global__ void __launch_bounds__(256, 2) sim_kernel() {
    extern __shared__ char sm[];
    const uint32_t sb = smem_u32(sm);
    const int tid = threadIdx.x;
    const int w = tid >> 5, l = tid & 31;
    const int rw = w >> 1, cw = w & 1;      // 4 row-groups of 32, 2 col-groups of 64

    // decode upper-triangular (ib <= jb) tile index
    const int t = blockIdx.x;
    int ib = (int)floorf((2.f * NB + 1.f -
              sqrtf((2.f * NB + 1.f) * (2.f * NB + 1.f) - 8.f * (float)t)) * 0.5f);
    if (ib < 0) ib = 0;
    if (ib > NB - 1) ib = NB - 1;
    #pragma unroll 1
    while (ib > 0 && ib * NB - (ib * (ib - 1)) / 2 > t) ib--;
    #pragma unroll 1
    while (ib < NB - 1 && (ib + 1) * NB - ((ib + 1) * ib) / 2 <= t) ib++;
    const int jb = ib + (t - (ib * NB - (ib * (ib - 1)) / 2));
    const bool diag = (ib == jb);

    float* red_row = (float*)(sm + S_RR);
    float* red_col = (float*)(sm + S_RC);
    if (tid < 128) { red_row[tid] = 0.f; red_col[tid] = 0.f; }

    // load A (block ib) and B (block jb): 128 rows x 128B each, swizzled
    {
        const char* gA = (const char*)g_fp8 + (size_t)ib * 128 * 128;
        const char* gB = (const char*)g_fp8 + (size_t)jb * 128 * 128;
        #pragma unroll
        for (int jj = 0; jj < 4; jj++) {
            const int idx = jj * 256 + tid, r = idx >> 3, c = idx & 7;
            const uint32_t off = (uint32_t)(r * 128 + ((c ^ (r & 7)) << 4));
            cp16(sb + S_A + off, gA + idx * 16);
            cp16(sb + S_B + off, gB + idx * 16);
        }
    }
    CP_COMMIT();
    CP_WAIT0();
    __syncthreads();

    // ldmatrix addresses (row pitch 128B)
    uint32_t aBase[2], bOff[4];
    #pragma unroll
    for (int mf = 0; mf < 2; mf++)
        aBase[mf] = sb + S_A + (uint32_t)((rw * 32 + mf * 16 + (l & 15)) * 128);
    const int bn = (l & 7) + ((l >> 4) << 3);
    #pragma unroll
    for (int nf2 = 0; nf2 < 4; nf2++)
        bOff[nf2] = sb + S_B + (uint32_t)((cw * 64 + nf2 * 16 + bn) * 128);
    const int akc = l >> 4;
    const int bkc = (l >> 3) & 1;
    const int sxor = l & 7;

    float acc[2][8][4];
    #pragma unroll
    for (int mf = 0; mf < 2; mf++)
        #pragma unroll
        for (int nf = 0; nf < 8; nf++)
            #pragma unroll
            for (int e = 0; e < 4; e++) acc[mf][nf][e] = 0.f;

    #pragma unroll
    for (int k = 0; k < 4; k++) {           // 4 k-steps of 32 fp8
        uint32_t a[2][4], b[4][4];
        #pragma unroll
        for (int mf = 0; mf < 2; mf++)
            ldsm4(a[mf], aBase[mf] + (((k * 2 + akc) ^ sxor) << 4));
        #pragma unroll
        for (int nf2 = 0; nf2 < 4; nf2++)
            ldsm4(b[nf2], bOff[nf2] + (((k * 2 + bkc) ^ sxor) << 4));
        #pragma unroll
        for (int mf = 0; mf < 2; mf++)
            #pragma unroll
            for (int nf = 0; nf < 8; nf++)
                mma_fp8(acc[mf][nf], a[mf], &b[nf >> 1][(nf & 1) * 2]);
    }

    // epilogue: exp2(acc/256) once per element; row partials and col partials
    float rpart[2][2] = {{0.f, 0.f}, {0.f, 0.f}};
    float cpart[8][2];
    #pragma unroll
    for (int nf = 0; nf < 8; nf++) { cpart[nf][0] = 0.f; cpart[nf][1] = 0.f; }

    #pragma unroll
    for (int mf = 0; mf < 2; mf++)
        #pragma unroll
        for (int nf = 0; nf < 8; nf++) {
            const float e0 = exp2f(acc[mf][nf][0] * INV_SC2);
            const float e1 = exp2f(acc[mf][nf][1] * INV_SC2);
            const float e2 = exp2f(acc[mf][nf][2] * INV_SC2);
            const float e3 = exp2f(acc[mf][nf][3] * INV_SC2);
            rpart[mf][0] += e0 + e1;
            rpart[mf][1] += e2 + e3;
            cpart[nf][0] += e0 + e2;
            cpart[nf][1] += e1 + e3;
        }

    // row sums: reduce across quad lanes
    #pragma unroll
    for (int off = 1; off <= 2; off <<= 1)
        #pragma unroll
        for (int mf = 0; mf < 2; mf++)
            #pragma unroll
            for (int h = 0; h < 2; h++)
                rpart[mf][h] += __shfl_xor_sync(0xffffffffu, rpart[mf][h], off);
    if ((l & 3) == 0) {
        #pragma unroll
        for (int mf = 0; mf < 2; mf++)
            #pragma unroll
            for (int h = 0; h < 2; h++)
                atomicAdd(&red_row[rw * 32 + mf * 16 + h * 8 + (l >> 2)], rpart[mf][h]);
    }

    // col sums: reduce across row lanes, off-diagonal only
    if (!diag) {
        #pragma unroll
        for (int off = 4; off <= 16; off <<= 1)
            #pragma unroll
            for (int nf = 0; nf < 8; nf++)
                #pragma unroll
                for (int p = 0; p < 2; p++)
                    cpart[nf][p] += __shfl_xor_sync(0xffffffffu, cpart[nf][p], off);
        if (l < 4) {
            #pragma unroll
            for (int nf = 0; nf < 8; nf++)
                #pragma unroll
                for (int p = 0; p < 2; p++)
                    atomicAdd(&red_col[cw * 64 + nf * 8 + l * 2 + p], cpart[nf][p]);
        }
    }
    __syncthreads();

    if (tid < 128) {
        atomicAdd(&g_rowsum[ib * 128 + tid], red_row[tid]);
        if (!diag) atomicAdd(&g_rowsum[jb * 128 + tid], red_col[tid]);
    }
}

// ---------------- Phase 3: per-row contrib, block-reduce, atomic into out --
__global__ void __launch_bounds__(256) finrow_kernel(float* __restrict__ out) {
    __shared__ float ws[8];
    const int i = blockIdx.x * 256 + threadIdx.x;
    const float s = g_rowsum[i];

    // sii from the fp8 copy: cancels the diagonal term in s self-consistently
    const __nv_fp8_e4m3* q = (const __nv_fp8_e4m3*)g_fp8 + (size_t)i * DD;
    float sii = 0.f;
    #pragma unroll
    for (int k = 0; k < DD; k++) { const float v = float(q[k]); sii += v * v; }

    // positive pair from the bf16 copy (scale sqrt(log2e))
    const __nv_bfloat162* a = (const __nv_bfloat162*)g_bf4 + (size_t)i * 64;
    const __nv_bfloat162* b = (const __nv_bfloat162*)g_bf4 + (size_t)(i ^ 1) * 64;
    float pos = 0.f;
    #pragma unroll
    for (int k = 0; k < 64; k++) {
        const float2 av = __bfloat1622float2(a[k]);
        const float2 bv = __bfloat1622float2(b[k]);
        pos += av.x * bv.x + av.y * bv.y;
    }

    float contrib = logf(s + 1.f - exp2f(sii * INV_SC2)) - pos * LN2F;

    #pragma unroll
    for (int o = 16; o; o >>= 1) contrib += __shfl_xor_sync(0xffffffffu, contrib, o);
    if ((threadIdx.x & 31) == 0) ws[threadIdx.x >> 5] = contrib;
    __syncthreads();
    if (threadIdx.x < 8) {
        float acc = ws[threadIdx.x];
        #pragma unroll
        for (int o = 4; o; o >>= 1) acc += __shfl_xor_sync(0x000000ffu, acc, o);
        if (threadIdx.x == 0) atomicAdd(out, acc * (1.f / (float)NN));
    }
}

extern "C" void kernel_launch(void* const* d_in, const int* in_sizes, int n_in,
                              void* d_out, int out_size) {
    const float* l1 = (const float*)d_in[0];
    const float* l2 = (const float*)d_in[1];
    float* out = (float*)d_out;

    cudaFuncSetAttribute(sim_kernel, cudaFuncAttributeMaxDynamicSharedMemorySize, S_TOT);

    prep_kernel<<<NN / 8, 256>>>(l1, l2, out);
    sim_kernel<<<NB * (NB + 1) / 2, 256, S_TOT>>>();
    finrow_kernel<<<NN / 256, 256>>>(out);
}

// round 7
// speedup vs baseline: 1.4495x; 1.4495x over previous
#include <cuda_runtime.h>
#include <cuda_bf16.h>
#include <math.h>
#include <stdint.h>

// ExamplarLoss fused, symmetric, strip-mined: S = Lhat@Lhat^T on upper-tri
// 128x128 tiles via bf16 mma.sync; each CTA owns a 128x512 strip (<=4 tiles),
// A loaded once, B double-buffered via cp.async. |S|<=1 -> max-free sum of
// exp2 (data pre-scaled by sqrt(log2e)). pos + diag terms precomputed in prep.

#define NN 8192
#define DD 128
#define NB 64            // 64 row-blocks of 128
#define NSTRIPS 544      // sum over ib of ceil((NB-ib)/4)

__device__ uint4  g_bf4[NN * DD / 8];   // normalized*sqrt(log2e) rows, bf16 (2 MB)
__device__ float  g_rowsum[NN];         // per-row sum of exp2 (atomic accum)
__device__ float  g_pos[NN];            // fp32 cosine of positive pair
__device__ float  g_sii[NN];            // bf16-consistent diagonal (log2 units)

#define SQRT_LOG2E 1.2011224087864498f

// ------------------------- PTX helpers (base ISA) -------------------------
__device__ __forceinline__ uint32_t smem_u32(const void* p) {
    uint32_t a;
    asm("{ .reg .u64 t; cvta.to.shared.u64 t, %1; cvt.u32.u64 %0, t; }" : "=r"(a) : "l"(p));
    return a;
}
__device__ __forceinline__ void cp16(uint32_t dst, const void* src) {
    asm volatile("cp.async.cg.shared.global [%0], [%1], 16;" :: "r"(dst), "l"(src));
}
#define CP_COMMIT() asm volatile("cp.async.commit_group;" ::: "memory")
#define CP_WAIT1()  asm volatile("cp.async.wait_group 1;" ::: "memory")

__device__ __forceinline__ void ldsm4(uint32_t (&r)[4], uint32_t addr) {
    asm volatile("ldmatrix.sync.aligned.m8n8.x4.shared.b16 {%0,%1,%2,%3}, [%4];"
                 : "=r"(r[0]), "=r"(r[1]), "=r"(r[2]), "=r"(r[3]) : "r"(addr));
}
__device__ __forceinline__ void mma16816(float (&d)[4], const uint32_t (&a)[4],
                                         const uint32_t* b) {
    asm volatile("mma.sync.aligned.m16n8k16.row.col.f32.bf16.bf16.f32 "
                 "{%0,%1,%2,%3}, {%4,%5,%6,%7}, {%8,%9}, {%0,%1,%2,%3};"
                 : "+f"(d[0]), "+f"(d[1]), "+f"(d[2]), "+f"(d[3])
                 : "r"(a[0]), "r"(a[1]), "r"(a[2]), "r"(a[3]), "r"(b[0]), "r"(b[1]));
}

// ---------------- Phase 1: per-pair normalize + pos + sii; zero accums -----
// One warp per sample pair p: rows 2p (from l1) and 2p+1 (from l2).
__global__ void __launch_bounds__(256) prep_kernel(const float* __restrict__ l1,
                                                   const float* __restrict__ l2,
                                                   float* __restrict__ out) {
    const int p = blockIdx.x * 8 + (threadIdx.x >> 5);
    const int lane = threadIdx.x & 31;
    if (threadIdx.x < 16) g_rowsum[blockIdx.x * 16 + threadIdx.x] = 0.f;
    if (blockIdx.x == 0 && threadIdx.x == 0) out[0] = 0.f;

    const float4 v1 = ((const float4*)(l1 + (size_t)p * DD))[lane];
    const float4 v2 = ((const float4*)(l2 + (size_t)p * DD))[lane];
    float sq1 = v1.x * v1.x + v1.y * v1.y + v1.z * v1.z + v1.w * v1.w;
    float sq2 = v2.x * v2.x + v2.y * v2.y + v2.z * v2.z + v2.w * v2.w;
    float dot = v1.x * v2.x + v1.y * v2.y + v1.z * v2.z + v1.w * v2.w;
    #pragma unroll
    for (int o = 16; o; o >>= 1) {
        sq1 += __shfl_xor_sync(0xffffffffu, sq1, o);
        sq2 += __shfl_xor_sync(0xffffffffu, sq2, o);
        dot += __shfl_xor_sync(0xffffffffu, dot, o);
    }
    const float inv1 = rsqrtf(sq1), inv2 = rsqrtf(sq2);
    const float c1 = inv1 * SQRT_LOG2E, c2 = inv2 * SQRT_LOG2E;

    // bf16 rows (scaled by sqrt(log2e))
    __nv_bfloat162 a0 = __floats2bfloat162_rn(v1.x * c1, v1.y * c1);
    __nv_bfloat162 a1 = __floats2bfloat162_rn(v1.z * c1, v1.w * c1);
    __nv_bfloat162 b0 = __floats2bfloat162_rn(v2.x * c2, v2.y * c2);
    __nv_bfloat162 b1 = __floats2bfloat162_rn(v2.z * c2, v2.w * c2);
    uint2 pk1, pk2;
    pk1.x = *(uint32_t*)&a0; pk1.y = *(uint32_t*)&a1;
    pk2.x = *(uint32_t*)&b0; pk2.y = *(uint32_t*)&b1;
    ((uint2*)g_bf4)[(size_t)(2 * p) * 32 + lane] = pk1;
    ((uint2*)g_bf4)[(size_t)(2 * p + 1) * 32 + lane] = pk2;

    // diagonal terms, computed from the bf16-rounded values (GEMM-consistent)
    const float2 fa0 = __bfloat1622float2(a0), fa1 = __bfloat1622float2(a1);
    const float2 fb0 = __bfloat1622float2(b0), fb1 = __bfloat1622float2(b1);
    float s1 = fa0.x * fa0.x + fa0.y * fa0.y + fa1.x * fa1.x + fa1.y * fa1.y;
    float s2 = fb0.x * fb0.x + fb0.y * fb0.y + fb1.x * fb1.x + fb1.y * fb1.y;
    #pragma unroll
    for (int o = 16; o; o >>= 1) {
        s1 += __shfl_xor_sync(0xffffffffu, s1, o);
        s2 += __shfl_xor_sync(0xffffffffu, s2, o);
    }
    if (lane == 0) {
        const float pos = dot * inv1 * inv2;   // fp32 cosine S[2p, 2p+1]
        g_pos[2 * p] = pos;
        g_pos[2 * p + 1] = pos;
        g_sii[2 * p] = s1;
        g_sii[2 * p + 1] = s2;
    }
}

// ---------------- Phase 2: strip-mined symmetric HMMA + fused sum-exp2 -----
// SMEM: A 32KB | B buf0 32KB | B buf1 32KB
#define S_A    0
#define S_B    32768
#define S_TOT  98304

__global__ void __launch_bounds__(256, 2) sim_kernel() {
    extern __shared__ char sm[];
    const uint32_t sb = smem_u32(sm);
    const int tid = threadIdx.x;
    const int w = tid >> 5, l = tid & 31;
    const int rw = w >> 1, cw = w & 1;      // 4 row-groups of 32, 2 col-groups of 64

    // decode strip: (ib, jb0) with jb0 = ib + 4*s
    int t = blockIdx.x, ib = 0, base = 0;
    #pragma unroll 1
    for (; ib < NB; ib++) {
        const int ns = (NB - ib + 3) >> 2;
        if (base + ns > t) break;
        base += ns;
    }
    const int jb0 = ib + ((t - base) << 2);
    const int ntiles = (NB - jb0 < 4) ? (NB - jb0) : 4;

    // load A(ib) + B(jb0) into buf0 (swizzled) -> group 0
    {
        const char* gA = (const char*)g_bf4 + (size_t)ib * 128 * 256;
        const char* gB = (const char*)g_bf4 + (size_t)jb0 * 128 * 256;
        #pragma unroll
        for (int jj = 0; jj < 8; jj++) {
            const int idx = jj * 256 + tid, r = idx >> 4, c = idx & 15;
            const uint32_t off = (uint32_t)(r * 256 + ((c ^ (r & 7)) << 4));
            cp16(sb + S_A + off, gA + idx * 16);
            cp16(sb + S_B + off, gB + idx * 16);
        }
    }
    CP_COMMIT();
    // prefetch B(jb0+1) into buf1 -> group 1
    if (ntiles > 1) {
        const char* gB = (const char*)g_bf4 + (size_t)(jb0 + 1) * 128 * 256;
        #pragma unroll
        for (int jj = 0; jj < 8; jj++) {
            const int idx = jj * 256 + tid, r = idx >> 4, c = idx & 15;
            cp16(sb + S_B + 32768 + (uint32_t)(r * 256 + ((c ^ (r & 7)) << 4)), gB + idx * 16);
        }
    }
    CP_COMMIT();
    CP_WAIT1();          // A + B(jb0) ready
    __syncthreads();

    // per-thread ldmatrix addressing (identical mapping to the validated R4 kernel)
    uint32_t aBase[2], bRel[4];
    #pragma unroll
    for (int mf = 0; mf < 2; mf++)
        aBase[mf] = sb + S_A + (uint32_t)((rw * 32 + mf * 16 + (l & 15)) * 256);
    const int bn = (l & 7) + ((l >> 4) << 3);
    #pragma unroll
    for (int nf2 = 0; nf2 < 4; nf2++)
        bRel[nf2] = (uint32_t)((cw * 64 + nf2 * 16 + bn) * 256);
    const int akc = l >> 4;
    const int bkc = (l >> 3) & 1;
    const int sxor = l & 7;

    float rpart[2][2] = {{0.f, 0.f}, {0.f, 0.f}};

    #pragma unroll 1
    for (int tt = 0; tt < ntiles; tt++) {
        const int jb = jb0 + tt;
        const bool diag = (jb == ib);
        const uint32_t bb = sb + S_B + (uint32_t)((tt & 1) * 32768);

        float acc[2][8][4];
        #pragma unroll
        for (int mf = 0; mf < 2; mf++)
            #pragma unroll
            for (int nf = 0; nf < 8; nf++)
                #pragma unroll
                for (int e = 0; e < 4; e++) acc[mf][nf][e] = 0.f;

        #pragma unroll
        for (int k = 0; k < 8; k++) {
            uint32_t a[2][4], b[4][4];
            #pragma unroll
            for (int mf = 0; mf < 2; mf++)
                ldsm4(a[mf], aBase[mf] + (((k * 2 + akc) ^ sxor) << 4));
            #pragma unroll
            for (int nf2 = 0; nf2 < 4; nf2++)
                ldsm4(b[nf2], bb + bRel[nf2] + (((k * 2 + bkc) ^ sxor) << 4));
            #pragma unroll
            for (int mf = 0; mf < 2; mf++)
                #pragma unroll
                for (int nf = 0; nf < 8; nf++)
                    mma16816(acc[mf][nf], a[mf], &b[nf >> 1][(nf & 1) * 2]);
        }

        // epilogue: exp2 once per element; rows accumulate, cols reduce+atomic
        float cpart[8][2];
        #pragma unroll
        for (int nf = 0; nf < 8; nf++) { cpart[nf][0] = 0.f; cpart[nf][1] = 0.f; }
        #pragma unroll
        for (int mf = 0; mf < 2; mf++)
            #pragma unroll
            for (int nf = 0; nf < 8; nf++) {
                const float e0 = exp2f(acc[mf][nf][0]);
                const float e1 = exp2f(acc[mf][nf][1]);
                const float e2 = exp2f(acc[mf][nf][2]);
                const float e3 = exp2f(acc[mf][nf][3]);
                rpart[mf][0] += e0 + e1;
                rpart[mf][1] += e2 + e3;
                cpart[nf][0] += e0 + e2;
                cpart[nf][1] += e1 + e3;
            }
        if (!diag) {
            #pragma unroll
            for (int off = 4; off <= 16; off <<= 1)
                #pragma unroll
                for (int nf = 0; nf < 8; nf++)
                    #pragma unroll
                    for (int pp = 0; pp < 2; pp++)
                        cpart[nf][pp] += __shfl_xor_sync(0xffffffffu, cpart[nf][pp], off);
            if (l < 4) {
                #pragma unroll
                for (int nf = 0; nf < 8; nf++)
                    #pragma unroll
                    for (int pp = 0; pp < 2; pp++)
                        atomicAdd(&g_rowsum[jb * 128 + cw * 64 + nf * 8 + l * 2 + pp],
                                  cpart[nf][pp]);
            }
        }

        __syncthreads();                       // all warps done reading buf tt&1
        if (tt + 2 < ntiles) {                 // prefetch B(tt+2) into buf tt&1
            const char* gB = (const char*)g_bf4 + (size_t)(jb0 + tt + 2) * 128 * 256;
            const uint32_t bw = sb + S_B + (uint32_t)((tt & 1) * 32768);
            #pragma unroll
            for (int jj = 0; jj < 8; jj++) {
                const int idx = jj * 256 + tid, r = idx >> 4, c = idx & 15;
                cp16(bw + (uint32_t)(r * 256 + ((c ^ (r & 7)) << 4)), gB + idx * 16);
            }
        }
        CP_COMMIT();
        CP_WAIT1();                            // B(tt+1) ready
        __syncthreads();
    }

    // row sums: reduce across quad lanes, atomic once per strip
    #pragma unroll
    for (int off = 1; off <= 2; off <<= 1)
        #pragma unroll
        for (int mf = 0; mf < 2; mf++)
            #pragma unroll
            for (int h = 0; h < 2; h++)
                rpart[mf][h] += __shfl_xor_sync(0xffffffffu, rpart[mf][h], off);
    if ((l & 3) == 0) {
        #pragma unroll
        for (int mf = 0; mf < 2; mf++)
            #pragma unroll
            for (int h = 0; h < 2; h++)
                atomicAdd(&g_rowsum[ib * 128 + rw * 32 + mf * 16 + h * 8 + (l >> 2)],
                          rpart[mf][h]);
    }
}

// ---------------- Phase 3: per-row contrib, block-reduce, atomic into out --
__global__ void __launch_bounds__(256) finrow_kernel(float* __restrict__ out) {
    __shared__ float ws[8];
    const int i = blockIdx.x * 256 + threadIdx.x;
    // g_rowsum includes exp2(sii) on the diagonal; reference zeroes diag -> +1
    float contrib = logf(g_rowsum[i] + 1.f - exp2f(g_sii[i])) - g_pos[i];
    #pragma unroll
    for (int o = 16; o; o >>= 1) contrib += __shfl_xor_sync(0xffffffffu, contrib, o);
    if ((threadIdx.x & 31) == 0) ws[threadIdx.x >> 5] = contrib;
    __syncthreads();
    if (threadIdx.x < 8) {
        float acc = ws[threadIdx.x];
        #pragma unroll
        for (int o = 4; o; o >>= 1) acc += __shfl_xor_sync(0x000000ffu, acc, o);
        if (threadIdx.x == 0) atomicAdd(out, acc * (1.f / (float)NN));
    }
}

extern "C" void kernel_launch(void* const* d_in, const int* in_sizes, int n_in,
                              void* d_out, int out_size) {
    const float* l1 = (const float*)d_in[0];
    const float* l2 = (const float*)d_in[1];
    float* out = (float*)d_out;

    cudaFuncSetAttribute(sim_kernel, cudaFuncAttributeMaxDynamicSharedMemorySize, S_TOT);

    prep_kernel<<<NN / 16, 256>>>(l1, l2, out);   // one warp per pair
    sim_kernel<<<NSTRIPS, 256, S_TOT>>>();
    finrow_kernel<<<NN / 256, 256>>>(out);
}

// round 8
// speedup vs baseline: 1.5316x; 1.0567x over previous
#include <cuda_runtime.h>
#include <cuda_bf16.h>
#include <math.h>
#include <stdint.h>

// ExamplarLoss fused, symmetric, balanced single-wave schedule:
// 2080 upper-tri 128x128 tiles partitioned into 296 strips over the global
// tile enumeration (8 strips of 8 + 288 of 7) -> every SM gets 14-15 tiles.
// bf16 mma.sync, B double-buffered, A reloaded on row-block crossings.
// |S|<=1 -> max-free sum of exp2 (data pre-scaled by sqrt(log2e)).
// Diagonal correction uses exp2(sii) ~= e (error ~1e-7); pos precomputed fp32.

#define NN 8192
#define DD 128
#define NB 64
#define NSTRIPS 296

__device__ uint4  g_bf4[NN * DD / 8];   // normalized*sqrt(log2e) rows, bf16 (2 MB)
__device__ float  g_rowsum[NN];         // per-row sum of exp2 (atomic accum)
__device__ float  g_pos[NN];            // fp32 cosine of positive pair

#define SQRT_LOG2E 1.2011224087864498f
#define E_CONST    2.718281828459045f

// ------------------------- PTX helpers (base ISA) -------------------------
__device__ __forceinline__ uint32_t smem_u32(const void* p) {
    uint32_t a;
    asm("{ .reg .u64 t; cvta.to.shared.u64 t, %1; cvt.u32.u64 %0, t; }" : "=r"(a) : "l"(p));
    return a;
}
__device__ __forceinline__ void cp16(uint32_t dst, const void* src) {
    asm volatile("cp.async.cg.shared.global [%0], [%1], 16;" :: "r"(dst), "l"(src));
}
#define CP_COMMIT() asm volatile("cp.async.commit_group;" ::: "memory")
#define CP_WAIT1()  asm volatile("cp.async.wait_group 1;" ::: "memory")

__device__ __forceinline__ void ldsm4(uint32_t (&r)[4], uint32_t addr) {
    asm volatile("ldmatrix.sync.aligned.m8n8.x4.shared.b16 {%0,%1,%2,%3}, [%4];"
                 : "=r"(r[0]), "=r"(r[1]), "=r"(r[2]), "=r"(r[3]) : "r"(addr));
}
__device__ __forceinline__ void mma16816(float (&d)[4], const uint32_t (&a)[4],
                                         const uint32_t* b) {
    asm volatile("mma.sync.aligned.m16n8k16.row.col.f32.bf16.bf16.f32 "
                 "{%0,%1,%2,%3}, {%4,%5,%6,%7}, {%8,%9}, {%0,%1,%2,%3};"
                 : "+f"(d[0]), "+f"(d[1]), "+f"(d[2]), "+f"(d[3])
                 : "r"(a[0]), "r"(a[1]), "r"(a[2]), "r"(a[3]), "r"(b[0]), "r"(b[1]));
}

// ---------------- Phase 1: normalize -> bf16*sqrt(log2e) + pos; zero accums
// One warp per TWO pairs (4 rows): 4 independent LDG.128 per thread (MLP=4).
__global__ void __launch_bounds__(256) prep_kernel(const float* __restrict__ l1,
                                                   const float* __restrict__ l2,
                                                   float* __restrict__ out) {
    const int tid = threadIdx.x;
    const int q = blockIdx.x * 8 + (tid >> 5);   // warp id, 0..2047
    const int lane = tid & 31;
    if (tid < 32) g_rowsum[blockIdx.x * 32 + tid] = 0.f;
    if (blockIdx.x == 0 && tid == 0) out[0] = 0.f;

    const int pA = 2 * q, pB = 2 * q + 1;
    const float4 a1 = ((const float4*)(l1 + (size_t)pA * DD))[lane];
    const float4 a2 = ((const float4*)(l2 + (size_t)pA * DD))[lane];
    const float4 b1 = ((const float4*)(l1 + (size_t)pB * DD))[lane];
    const float4 b2 = ((const float4*)(l2 + (size_t)pB * DD))[lane];

    float sa1 = a1.x * a1.x + a1.y * a1.y + a1.z * a1.z + a1.w * a1.w;
    float sa2 = a2.x * a2.x + a2.y * a2.y + a2.z * a2.z + a2.w * a2.w;
    float da  = a1.x * a2.x + a1.y * a2.y + a1.z * a2.z + a1.w * a2.w;
    float sb1 = b1.x * b1.x + b1.y * b1.y + b1.z * b1.z + b1.w * b1.w;
    float sb2 = b2.x * b2.x + b2.y * b2.y + b2.z * b2.z + b2.w * b2.w;
    float db  = b1.x * b2.x + b1.y * b2.y + b1.z * b2.z + b1.w * b2.w;
    #pragma unroll
    for (int o = 16; o; o >>= 1) {
        sa1 += __shfl_xor_sync(0xffffffffu, sa1, o);
        sa2 += __shfl_xor_sync(0xffffffffu, sa2, o);
        da  += __shfl_xor_sync(0xffffffffu, da, o);
        sb1 += __shfl_xor_sync(0xffffffffu, sb1, o);
        sb2 += __shfl_xor_sync(0xffffffffu, sb2, o);
        db  += __shfl_xor_sync(0xffffffffu, db, o);
    }
    const float ia1 = rsqrtf(sa1), ia2 = rsqrtf(sa2);
    const float ib1 = rsqrtf(sb1), ib2 = rsqrtf(sb2);

    #pragma unroll
    for (int r = 0; r < 4; r++) {
        const float4 v = (r == 0) ? a1 : (r == 1) ? a2 : (r == 2) ? b1 : b2;
        const float c = ((r == 0) ? ia1 : (r == 1) ? ia2 : (r == 2) ? ib1 : ib2) * SQRT_LOG2E;
        __nv_bfloat162 p0 = __floats2bfloat162_rn(v.x * c, v.y * c);
        __nv_bfloat162 p1 = __floats2bfloat162_rn(v.z * c, v.w * c);
        uint2 pk;
        pk.x = *(uint32_t*)&p0;
        pk.y = *(uint32_t*)&p1;
        ((uint2*)g_bf4)[(size_t)(4 * q + r) * 32 + lane] = pk;
    }
    if (lane == 0) {
        const float posA = da * ia1 * ia2;
        const float posB = db * ib1 * ib2;
        g_pos[4 * q + 0] = posA;
        g_pos[4 * q + 1] = posA;
        g_pos[4 * q + 2] = posB;
        g_pos[4 * q + 3] = posB;
    }
}

// ---------------- Phase 2: balanced symmetric HMMA + fused sum-exp2 --------
// SMEM: A 32KB | B buf0 32KB | B buf1 32KB
#define S_A    0
#define S_B    32768
#define S_TOT  98304

__device__ __forceinline__ void load_tile(uint32_t dst, int blk, int tid) {
    const char* src = (const char*)g_bf4 + (size_t)blk * 128 * 256;
    #pragma unroll
    for (int jj = 0; jj < 8; jj++) {
        const int idx = jj * 256 + tid, r = idx >> 4, c = idx & 15;
        cp16(dst + (uint32_t)(r * 256 + ((c ^ (r & 7)) << 4)), src + idx * 16);
    }
}

__global__ void __launch_bounds__(256, 2) sim_kernel() {
    extern __shared__ char sm[];
    const uint32_t sb = smem_u32(sm);
    const int tid = threadIdx.x;
    const int w = tid >> 5, l = tid & 31;
    const int rw = w >> 1, cw = w & 1;

    // strip: first 8 CTAs take 8 tiles each (row 0), rest take 7
    const int bid = blockIdx.x;
    int off, len;
    if (bid < 8) { off = bid * 8; len = 8; }
    else         { off = 64 + (bid - 8) * 7; len = 7; }

    // decode off -> (ib, jb) in the row-major upper-tri enumeration
    int ib = 0;
    while (64 * (ib + 1) - ((ib + 1) * ib) / 2 <= off) ib++;
    int jb = ib + (off - (64 * ib - (ib * (ib - 1)) / 2));

    // prologue: A(ib) + B(jb) -> group 0; B(next) -> group 1
    load_tile(sb + S_A, ib, tid);
    load_tile(sb + S_B, jb, tid);
    CP_COMMIT();
    int ibn = ib, jbn = jb;                  // coords of tile t+1
    { jbn++; if (jbn == NB) { ibn++; jbn = ibn; } }
    load_tile(sb + S_B + 32768, jbn, tid);   // len >= 7, always valid
    CP_COMMIT();
    CP_WAIT1();
    __syncthreads();

    // per-thread ldmatrix addressing (validated mapping)
    uint32_t aBase[2], bRel[4];
    #pragma unroll
    for (int mf = 0; mf < 2; mf++)
        aBase[mf] = sb + S_A + (uint32_t)((rw * 32 + mf * 16 + (l & 15)) * 256);
    const int bn = (l & 7) + ((l >> 4) << 3);
    #pragma unroll
    for (int nf2 = 0; nf2 < 4; nf2++)
        bRel[nf2] = (uint32_t)((cw * 64 + nf2 * 16 + bn) * 256);
    const int akc = l >> 4;
    const int bkc = (l >> 3) & 1;
    const int sxor = l & 7;

    float rpart[2][2] = {{0.f, 0.f}, {0.f, 0.f}};
    int ibc = ib, jbc = jb;

    #pragma unroll 1
    for (int t = 0; t < len; t++) {
        const bool diag = (ibc == jbc);
        const uint32_t bb = sb + S_B + (uint32_t)((t & 1) * 32768);

        float acc[2][8][4];
        #pragma unroll
        for (int mf = 0; mf < 2; mf++)
            #pragma unroll
            for (int nf = 0; nf < 8; nf++)
                #pragma unroll
                for (int e = 0; e < 4; e++) acc[mf][nf][e] = 0.f;

        #pragma unroll
        for (int k = 0; k < 8; k++) {
            uint32_t a[2][4], b[4][4];
            #pragma unroll
            for (int mf = 0; mf < 2; mf++)
                ldsm4(a[mf], aBase[mf] + (((k * 2 + akc) ^ sxor) << 4));
            #pragma unroll
            for (int nf2 = 0; nf2 < 4; nf2++)
                ldsm4(b[nf2], bb + bRel[nf2] + (((k * 2 + bkc) ^ sxor) << 4));
            #pragma unroll
            for (int mf = 0; mf < 2; mf++)
                #pragma unroll
                for (int nf = 0; nf < 8; nf++)
                    mma16816(acc[mf][nf], a[mf], &b[nf >> 1][(nf & 1) * 2]);
        }

        // epilogue: exp2 once per element
        float cpart[8][2];
        #pragma unroll
        for (int nf = 0; nf < 8; nf++) { cpart[nf][0] = 0.f; cpart[nf][1] = 0.f; }
        #pragma unroll
        for (int mf = 0; mf < 2; mf++)
            #pragma unroll
            for (int nf = 0; nf < 8; nf++) {
                const float e0 = exp2f(acc[mf][nf][0]);
                const float e1 = exp2f(acc[mf][nf][1]);
                const float e2 = exp2f(acc[mf][nf][2]);
                const float e3 = exp2f(acc[mf][nf][3]);
                rpart[mf][0] += e0 + e1;
                rpart[mf][1] += e2 + e3;
                cpart[nf][0] += e0 + e2;
                cpart[nf][1] += e1 + e3;
            }
        if (!diag) {
            #pragma unroll
            for (int o = 4; o <= 16; o <<= 1)
                #pragma unroll
                for (int nf = 0; nf < 8; nf++)
                    #pragma unroll
                    for (int pp = 0; pp < 2; pp++)
                        cpart[nf][pp] += __shfl_xor_sync(0xffffffffu, cpart[nf][pp], o);
            if (l < 4) {
                #pragma unroll
                for (int nf = 0; nf < 8; nf++)
                    #pragma unroll
                    for (int pp = 0; pp < 2; pp++)
                        atomicAdd(&g_rowsum[jbc * 128 + cw * 64 + nf * 8 + l * 2 + pp],
                                  cpart[nf][pp]);
            }
        }

        __syncthreads();   // A + current B buffer free; cpart atomics done

        const bool last = (t == len - 1);
        const bool achange = !last && (ibn != ibc);

        if (achange) {                       // reload A for next tile's row
            load_tile(sb + S_A, ibn, tid);
            CP_COMMIT();
        }
        if (t + 2 < len) {                   // prefetch B(t+2)
            int ib2 = ibn, jb2 = jbn;
            { jb2++; if (jb2 == NB) { ib2++; jb2 = ib2; } }
            load_tile(sb + S_B + (uint32_t)((t & 1) * 32768), jb2, tid);
        }
        CP_COMMIT();

        if (achange || last) {               // flush row partials for block ibc
            float rp[2][2] = {{rpart[0][0], rpart[0][1]}, {rpart[1][0], rpart[1][1]}};
            #pragma unroll
            for (int o = 1; o <= 2; o <<= 1)
                #pragma unroll
                for (int mf = 0; mf < 2; mf++)
                    #pragma unroll
                    for (int h = 0; h < 2; h++)
                        rp[mf][h] += __shfl_xor_sync(0xffffffffu, rp[mf][h], o);
            if ((l & 3) == 0) {
                #pragma unroll
                for (int mf = 0; mf < 2; mf++)
                    #pragma unroll
                    for (int h = 0; h < 2; h++)
                        atomicAdd(&g_rowsum[ibc * 128 + rw * 32 + mf * 16 + h * 8 + (l >> 2)],
                                  rp[mf][h]);
            }
            rpart[0][0] = rpart[0][1] = rpart[1][0] = rpart[1][1] = 0.f;
        }

        if (!last) {
            CP_WAIT1();                      // retires B(t+1) (and A' if any)
            __syncthreads();
            ibc = ibn; jbc = jbn;
            { jbn++; if (jbn == NB) { ibn++; jbn = ibn; } }
        }
    }
}

// ---------------- Phase 3: per-row contrib, block-reduce, atomic into out --
__global__ void __launch_bounds__(256) finrow_kernel(float* __restrict__ out) {
    __shared__ float ws[8];
    const int i = blockIdx.x * 256 + threadIdx.x;
    // rowsum includes exp2(sii) ~= e on the diagonal; reference wants exp(0)=1
    float contrib = logf(g_rowsum[i] + 1.f - E_CONST) - g_pos[i];
    #pragma unroll
    for (int o = 16; o; o >>= 1) contrib += __shfl_xor_sync(0xffffffffu, contrib, o);
    if ((threadIdx.x & 31) == 0) ws[threadIdx.x >> 5] = contrib;
    __syncthreads();
    if (threadIdx.x < 8) {
        float acc = ws[threadIdx.x];
        #pragma unroll
        for (int o = 4; o; o >>= 1) acc += __shfl_xor_sync(0x000000ffu, acc, o);
        if (threadIdx.x == 0) atomicAdd(out, acc * (1.f / (float)NN));
    }
}

extern "C" void kernel_launch(void* const* d_in, const int* in_sizes, int n_in,
                              void* d_out, int out_size) {
    const float* l1 = (const float*)d_in[0];
    const float* l2 = (const float*)d_in[1];
    float* out = (float*)d_out;

    cudaFuncSetAttribute(sim_kernel, cudaFuncAttributeMaxDynamicSharedMemorySize, S_TOT);

    prep_kernel<<<256, 256>>>(l1, l2, out);      // 2 pairs per warp
    sim_kernel<<<NSTRIPS, 256, S_TOT>>>();
    finrow_kernel<<<NN / 256, 256>>>(out);
}